// round 14
// baseline (speedup 1.0000x reference)
#include <cuda_runtime.h>
#include <cstdint>

// FiniteWindowTopologicalAttention — tf32 mma.sync GEMMs, race-free 2-stage
//   K0 : round weights -> tf32 copies    (tiny)
//   K1 : qkv = x @ w_qkv                 (tf32 mma, A rounded in-fragment)
//   K2 : windowed attention              (fp32; head-padded smem, conflict-free)
//   K3 : out = ao @ w_proj + b_proj      (tf32 mma)
//
// R14 change: attn smem head-slice padded 32 -> 36 floats. Old layout put the
// two per-warp LDS addresses (head h lanes 0-15, head h+1 lanes 16-31) exactly
// 128B apart = same bank group -> 2-way conflict on EVERY QK/PV LDS.128 (L1
// pipe was 94.2%). 144B spacing lands them on disjoint bank groups -> N=1.

#define D_MODEL 256
#define NQKV    768
#define M_TOK   262144          // 4 * 256 * 256
#define NWIN    16384           // 4 * 64 * 64

// scratch (allocation-free rule: __device__ globals)
__device__ float g_qkv   [(size_t)M_TOK * NQKV];     // 768 MB
__device__ float g_ao    [(size_t)M_TOK * D_MODEL];  // 256 MB (tf32-rounded)
__device__ float g_wqkv_r [D_MODEL * NQKV];
__device__ float g_wproj_r[D_MODEL * D_MODEL];

// ---------------- helpers -----------------------------------------------------
__device__ __forceinline__ float tf32r(float x) {
    uint32_t r;
    asm("cvt.rna.tf32.f32 %0, %1;" : "=r"(r) : "f"(x));
    return __uint_as_float(r);
}
__device__ __forceinline__ uint32_t tf32u(uint32_t x) {
    uint32_t r;
    asm("cvt.rna.tf32.f32 %0, %1;" : "=r"(r) : "f"(__uint_as_float(x)));
    return r;
}
__device__ __forceinline__ void mma_tf32(float c[4], const uint32_t a[4],
                                         const uint32_t b[2]) {
    asm volatile(
        "mma.sync.aligned.m16n8k8.row.col.f32.tf32.tf32.f32 "
        "{%0,%1,%2,%3}, {%4,%5,%6,%7}, {%8,%9}, {%0,%1,%2,%3};"
        : "+f"(c[0]), "+f"(c[1]), "+f"(c[2]), "+f"(c[3])
        : "r"(a[0]), "r"(a[1]), "r"(a[2]), "r"(a[3]), "r"(b[0]), "r"(b[1]));
}
__device__ __forceinline__ void cp16(uint32_t dst, const void* src) {
    asm volatile("cp.async.cg.shared.global [%0], [%1], 16;"
                 :: "r"(dst), "l"(src));
}

// ---------------- pre-pass kernel ---------------------------------------------
__global__ void round_w_kernel(const float* __restrict__ in,
                               float* __restrict__ out, int n)
{
    int i = blockIdx.x * blockDim.x + threadIdx.x;
    if (i < n) out[i] = tf32r(in[i]);
}

// ---------------- tf32 GEMM: C[M,N] = A[M,256] * B[256,N] (+bias) ------------
// BM=128, BN=128, BK=32. 128 threads = 4 warps (2m x 2n), warp tile 64x64.
// B pre-rounded; A rounded per-fragment iff ROUND_A (bit-identical numerics).
// Smem pitches: A 36 floats, B 136 floats -> fragment LDS conflict-free.
#define XS_F (128 * 36)          // 4608 floats
#define WS_F (32 * 136)          // 4352 floats
#define STAGE_F (XS_F + WS_F)    // 8960 floats
#define GEMM_SMEM_BYTES (2 * STAGE_F * 4)   // 71680 B

template<bool ROUND_A>
__global__ __launch_bounds__(128, 2)
void tf32_gemm_kernel(const float* __restrict__ A, const float* __restrict__ B,
                      float* __restrict__ C, const float* __restrict__ bias,
                      int N)
{
    extern __shared__ float smem[];
    const uint32_t sbase = (uint32_t)__cvta_generic_to_shared(smem);

    const int tid  = threadIdx.x;
    const int warp = tid >> 5, lane = tid & 31;
    const int wm = warp >> 1, wn = warp & 1;       // 2 x 2 warp grid, 64x64 each
    const int g  = lane >> 2, t = lane & 3;

    const size_t rowbase = (size_t)blockIdx.y * 128;
    const int    colbase = blockIdx.x * 128;

    float acc[4][8][4];
#pragma unroll
    for (int i = 0; i < 4; i++)
#pragma unroll
        for (int j = 0; j < 8; j++)
#pragma unroll
            for (int r = 0; r < 4; r++) acc[i][j][r] = 0.f;

    // tile copy: A 128x32 floats (1024 x 16B), B 32x128 (1024 x 16B); 8 each/thr
    auto issue_tile = [&](int kt, int buf) {
        uint32_t su = sbase + (uint32_t)(buf * STAGE_F * 4);
#pragma unroll
        for (int i = 0; i < 8; i++) {
            int ch = tid + i * 128;
            int r  = ch >> 3, kg = ch & 7;
            cp16(su + (uint32_t)((r * 36 + kg * 4) * 4),
                 A + (rowbase + r) * 256 + kt * 32 + kg * 4);
        }
#pragma unroll
        for (int i = 0; i < 8; i++) {
            int ch = tid + i * 128;
            int r  = ch >> 5, c = (ch & 31) << 2;
            cp16(su + (uint32_t)((XS_F + r * 136 + c) * 4),
                 B + (size_t)(kt * 32 + r) * N + colbase + c);
        }
        asm volatile("cp.async.commit_group;");
    };

    issue_tile(0, 0);

    for (int kt = 0; kt < 8; kt++) {
        // only tile kt can be outstanding here -> wait_group 0 makes it
        // resident; the barrier then proves every warp finished reading the
        // OTHER buffer (during iter kt-1) before we refill it below.
        asm volatile("cp.async.wait_group 0;");
        __syncthreads();

        if (kt < 7) issue_tile(kt + 1, (kt + 1) & 1);   // overlaps compute

        const uint32_t* xs = (const uint32_t*)(smem + (kt & 1) * STAGE_F);
        const uint32_t* ws = xs + XS_F;

#pragma unroll
        for (int k8 = 0; k8 < 4; k8++) {
            const int k0 = k8 * 8;
            uint32_t a[4][4];
#pragma unroll
            for (int i = 0; i < 4; i++) {
                const int r0 = wm * 64 + i * 16;
                a[i][0] = xs[(r0 + g)     * 36 + k0 + t];
                a[i][1] = xs[(r0 + g + 8) * 36 + k0 + t];
                a[i][2] = xs[(r0 + g)     * 36 + k0 + t + 4];
                a[i][3] = xs[(r0 + g + 8) * 36 + k0 + t + 4];
                if (ROUND_A) {
                    a[i][0] = tf32u(a[i][0]); a[i][1] = tf32u(a[i][1]);
                    a[i][2] = tf32u(a[i][2]); a[i][3] = tf32u(a[i][3]);
                }
            }
            uint32_t b[8][2];
#pragma unroll
            for (int j = 0; j < 8; j++) {
                const int c0 = wn * 64 + j * 8;
                b[j][0] = ws[(k0 + t)     * 136 + c0 + g];
                b[j][1] = ws[(k0 + t + 4) * 136 + c0 + g];
            }
#pragma unroll
            for (int i = 0; i < 4; i++)
#pragma unroll
                for (int j = 0; j < 8; j++) mma_tf32(acc[i][j], a[i], b[j]);
        }
    }

    // epilogue: c0,c1 -> (m, n..n+1); c2,c3 -> (m+8, n..n+1)
#pragma unroll
    for (int i = 0; i < 4; i++) {
        const size_t m0 = rowbase + wm * 64 + i * 16 + g;
#pragma unroll
        for (int j = 0; j < 8; j++) {
            const int n0 = colbase + wn * 64 + j * 8 + t * 2;
            float2 v0 = make_float2(acc[i][j][0], acc[i][j][1]);
            float2 v1 = make_float2(acc[i][j][2], acc[i][j][3]);
            if (bias) {
                float2 bb = *(const float2*)(bias + n0);
                v0.x += bb.x; v0.y += bb.y;
                v1.x += bb.x; v1.y += bb.y;
            }
            *(float2*)(C + m0 * N + n0)       = v0;
            *(float2*)(C + (m0 + 8) * N + n0) = v1;
        }
    }
}

// ---------------- Windowed attention (fp32, head-padded smem) -----------------
// One CTA per 4x4 window; 128 threads = 8 heads x 16 query rows.
// skv layout: [token][ K: h*36+d (0..287) | V: 288 + h*36+d ]  (pitch 576)
// 36-float head pitch => the two distinct warp addresses (h, h+1) are 144B
// apart = disjoint bank groups => conflict-free broadcast LDS.128.
#define HP   36                 // padded head pitch (floats)
#define TOKP 576                // per-token pitch: 8*36 (K) + 8*36 (V)

__global__ __launch_bounds__(128)
void attn_kernel(const float* __restrict__ qkv,
                 const float* __restrict__ rpb_table,
                 float* __restrict__ ao)
{
    __shared__ float skv [16 * TOKP];   // 36 KB
    __shared__ float srpb[49 * 8];

    const int tid = threadIdx.x;
    const int wid = blockIdx.x;
    const int b   = wid >> 12;
    const int tb  = (wid >> 6) & 63;
    const int sb_ = wid & 63;
    const int base = b * 65536 + tb * 1024 + sb_ * 4;

    for (int i = tid; i < 392; i += 128) srpb[i] = rpb_table[i];

    // stage K,V: qkv columns [256..768) for 16 tokens, repacked head-padded
#pragma unroll
    for (int i = 0; i < 16; i++) {
        int f = tid + i * 128;            // 0..2047 float4 chunks
        int tok = f >> 7;
        int c = f & 127;                  // float4 index within 512 floats
        int row = base + (tok >> 2) * 256 + (tok & 3);
        float4 v = *(const float4*)(qkv + (size_t)row * NQKV + 256 + c * 4);
        int dst;
        if (c < 64) {                     // K: head = c>>3, d = (c&7)*4
            dst = tok * TOKP + (c >> 3) * HP + (c & 7) * 4;
        } else {                          // V
            int c2 = c - 64;
            dst = tok * TOKP + 288 + (c2 >> 3) * HP + (c2 & 7) * 4;
        }
        *(float4*)&skv[dst] = v;
    }

    const int h  = tid >> 4;
    const int qi = tid & 15;
    const int qt = qi >> 2, qs = qi & 3;
    const int qrow = base + qt * 256 + qs;

    float4 qv[8];
    const float4* qp = (const float4*)(qkv + (size_t)qrow * NQKV + h * 32);
#pragma unroll
    for (int u = 0; u < 8; u++) qv[u] = qp[u];

    __syncthreads();

    const float scale = 0.17677669529663687f;   // 32^-0.5
    float sc[16];
#pragma unroll
    for (int j = 0; j < 16; j++) {
        const float4* kp = (const float4*)&skv[j * TOKP + h * HP];
        float a = 0.f;
#pragma unroll
        for (int u = 0; u < 8; u++) {
            float4 kv = kp[u];
            a += qv[u].x * kv.x + qv[u].y * kv.y + qv[u].z * kv.z + qv[u].w * kv.w;
        }
        int kt = j >> 2, ks = j & 3;
        int ridx = (qt - kt + 3) * 7 + (qs - ks + 3);
        sc[j] = a * scale + srpb[ridx * 8 + h];
    }

    float m = sc[0];
#pragma unroll
    for (int j = 1; j < 16; j++) m = fmaxf(m, sc[j]);
    float s = 0.f;
#pragma unroll
    for (int j = 0; j < 16; j++) { sc[j] = __expf(sc[j] - m); s += sc[j]; }
    const float inv = 1.f / s;

    float4 o[8];
#pragma unroll
    for (int u = 0; u < 8; u++) o[u] = make_float4(0.f, 0.f, 0.f, 0.f);
#pragma unroll
    for (int j = 0; j < 16; j++) {
        float w = sc[j] * inv;
        const float4* vp = (const float4*)&skv[j * TOKP + 288 + h * HP];
#pragma unroll
        for (int u = 0; u < 8; u++) {
            float4 vv = vp[u];
            o[u].x += w * vv.x; o[u].y += w * vv.y;
            o[u].z += w * vv.z; o[u].w += w * vv.w;
        }
    }

    // write tf32-rounded ao so K3 fragment loads need no cvt
    float4* op = (float4*)(ao + (size_t)qrow * D_MODEL + h * 32);
#pragma unroll
    for (int u = 0; u < 8; u++) {
        float4 v = o[u];
        v.x = tf32r(v.x); v.y = tf32r(v.y); v.z = tf32r(v.z); v.w = tf32r(v.w);
        op[u] = v;
    }
}

// ---------------- launch ------------------------------------------------------
extern "C" void kernel_launch(void* const* d_in, const int* in_sizes, int n_in,
                              void* d_out, int out_size)
{
    const float* x      = (const float*)d_in[0];   // (4,256,256,256)
    const float* w_qkv  = (const float*)d_in[1];   // (256,768)
    const float* w_proj = (const float*)d_in[2];   // (256,256)
    const float* b_proj = (const float*)d_in[3];   // (256,)
    const float* rpb    = (const float*)d_in[4];   // (49,8)
    float* out = (float*)d_out;

    float *qkv_p, *ao_p, *wq_p, *wp_p;
    cudaGetSymbolAddress((void**)&qkv_p, g_qkv);
    cudaGetSymbolAddress((void**)&ao_p,  g_ao);
    cudaGetSymbolAddress((void**)&wq_p,  g_wqkv_r);
    cudaGetSymbolAddress((void**)&wp_p,  g_wproj_r);

    cudaFuncSetAttribute(tf32_gemm_kernel<true>,
                         cudaFuncAttributeMaxDynamicSharedMemorySize,
                         GEMM_SMEM_BYTES);
    cudaFuncSetAttribute(tf32_gemm_kernel<false>,
                         cudaFuncAttributeMaxDynamicSharedMemorySize,
                         GEMM_SMEM_BYTES);

    // pre-round weights only (x is rounded in-fragment inside K1; ao is
    // rounded by the attention epilogue)
    round_w_kernel<<<(D_MODEL * NQKV) / 256, 256>>>(w_qkv, wq_p, D_MODEL * NQKV);
    round_w_kernel<<<(D_MODEL * D_MODEL) / 256, 256>>>(w_proj, wp_p,
                                                       D_MODEL * D_MODEL);

    // K1: qkv = x @ w_qkv  (A = raw x, rounded per-fragment)
    tf32_gemm_kernel<true><<<dim3(NQKV / 128, M_TOK / 128), 128,
                             GEMM_SMEM_BYTES>>>(x, wq_p, qkv_p, nullptr, NQKV);

    // K2: attention
    attn_kernel<<<NWIN, 128>>>(qkv_p, rpb, ao_p);

    // K3: out = ao @ w_proj + b_proj  (A = ao, already tf32)
    tf32_gemm_kernel<false><<<dim3(D_MODEL / 128, M_TOK / 128), 128,
                              GEMM_SMEM_BYTES>>>(ao_p, wp_p, out, b_proj,
                                                 D_MODEL);
}